// round 2
// baseline (speedup 1.0000x reference)
#include <cuda_runtime.h>
#include <cstdint>

#define T_TOKENS 1024
#define IN_DIM   4096
#define Q_DIM    4096
#define KV_DIM   1024
#define OUT_DIM  6144
#define NUM_D    4

#define BM 128
#define BN 128
#define BK 16
#define K_STEPS (IN_DIM / BK)   // 256

__device__ int   g_cnt[NUM_D];
__device__ int   g_perm[NUM_D][T_TOKENS];
__device__ float g_rowsum[T_TOKENS];

__global__ void reset_kernel() {
    if (threadIdx.x < NUM_D) g_cnt[threadIdx.x] = 0;
}

__global__ void group_kernel(const int* __restrict__ indices) {
    int t = blockIdx.x * blockDim.x + threadIdx.x;
    if (t < T_TOKENS) {
        int d = indices[t];
        int pos = atomicAdd(&g_cnt[d], 1);
        g_perm[d][pos] = t;
    }
}

__global__ void rowsum_kernel(const float* __restrict__ x) {
    int warp = (blockIdx.x * blockDim.x + threadIdx.x) >> 5;
    int lane = threadIdx.x & 31;
    if (warp >= T_TOKENS) return;
    const float4* xr = (const float4*)(x + (size_t)warp * IN_DIM);
    float s = 0.f;
    #pragma unroll 4
    for (int i = lane; i < IN_DIM / 4; i += 32) {
        float4 v = xr[i];
        s += (v.x + v.y) + (v.z + v.w);
    }
    #pragma unroll
    for (int off = 16; off > 0; off >>= 1) s += __shfl_down_sync(0xffffffffu, s, off);
    if (lane == 0) g_rowsum[warp] = s;
}

__device__ __forceinline__ unsigned long long pack2(float v) {
    unsigned long long r;
    asm("mov.b64 %0, {%1, %1};" : "=l"(r) : "f"(v));
    return r;
}
__device__ __forceinline__ void fma2(unsigned long long& acc,
                                     unsigned long long a, unsigned long long b) {
    asm("fma.rn.f32x2 %0, %1, %2, %0;" : "+l"(acc) : "l"(a), "l"(b));
}
__device__ __forceinline__ float2 unpack2(unsigned long long v) {
    float2 r;
    asm("mov.b64 {%0, %1}, %2;" : "=f"(r.x), "=f"(r.y) : "l"(v));
    return r;
}

__global__ void __launch_bounds__(256, 2)
fused_qkv_delta_kernel(
    const float* __restrict__ x, const float* __restrict__ w_base,
    const float* __restrict__ bias,
    const int* __restrict__ qw_q, const int* __restrict__ qw_k, const int* __restrict__ qw_v,
    const int* __restrict__ qz_q, const int* __restrict__ qz_k, const int* __restrict__ qz_v,
    const float* __restrict__ sc_q, const float* __restrict__ sc_k, const float* __restrict__ sc_v,
    float* __restrict__ out)
{
    const int d      = blockIdx.y >> 3;
    const int tile   = blockIdx.y & 7;
    const int cnt    = g_cnt[d];
    const int tstart = tile * BM;
    if (tstart >= cnt) return;
    const int nrows = min(BM, cnt - tstart);

    const int o0 = blockIdx.x * BN;
    const int* qw; const int* qz; const float* sc; int ol;
    if (o0 < Q_DIM) {
        ol = o0;
        qw = qw_q + (size_t)d * Q_DIM * (IN_DIM / 8);
        qz = qz_q + d * (Q_DIM / 8);
        sc = sc_q + d * Q_DIM;
    } else if (o0 < Q_DIM + KV_DIM) {
        ol = o0 - Q_DIM;
        qw = qw_k + (size_t)d * KV_DIM * (IN_DIM / 8);
        qz = qz_k + d * (KV_DIM / 8);
        sc = sc_k + d * KV_DIM;
    } else {
        ol = o0 - Q_DIM - KV_DIM;
        qw = qw_v + (size_t)d * KV_DIM * (IN_DIM / 8);
        qz = qz_v + d * (KV_DIM / 8);
        sc = sc_v + d * KV_DIM;
    }

    __shared__ __align__(16) float As[BK][BM];
    __shared__ __align__(16) float Bs[BK][BN];
    __shared__ float s_scz[BN];
    __shared__ int   s_tok[BM];

    const int tid  = threadIdx.x;
    const int row  = tid >> 1;
    const int half = tid & 1;
    const int tx   = tid & 15;
    const int ty   = tid >> 4;

    if (tid < BM) {
        s_tok[tid] = (tid < nrows) ? g_perm[d][tstart + tid] : -1;
    } else {
        int r  = tid - BM;
        int og = ol + r;
        int z  = (qz[og >> 3] >> ((og & 7) * 4)) & 0xF;
        s_scz[r] = sc[og] * (float)(z + 1);
    }
    const float sc_row = sc[ol + row];
    __syncthreads();

    const int  tok   = s_tok[row];
    const bool valid = tok >= 0;
    const float* xrow = x + (size_t)(valid ? tok : 0) * IN_DIM + half * 8;
    const float* wrow = w_base + (size_t)(o0 + row) * IN_DIM + half * 8;
    // FIX: index the quantized stack with the stack-local output row (ol + row),
    // not the tile-local row.
    const int*   qrow = qw + (size_t)(ol + row) * (IN_DIM / 8) + half;

    unsigned long long acc[4][8];
    #pragma unroll
    for (int i = 0; i < 4; i++)
        #pragma unroll
        for (int j = 0; j < 8; j++) acc[i][j] = 0ULL;

    float4 xa, xb, wa, wb4; int q;
    xa  = *(const float4*)(xrow + 0);
    xb  = *(const float4*)(xrow + 4);
    wa  = *(const float4*)(wrow + 0);
    wb4 = *(const float4*)(wrow + 4);
    q   = qrow[0];

    for (int kt = 0; kt < K_STEPS; kt++) {
        __syncthreads();
        if (valid) {
            As[half * 8 + 0][row] = xa.x; As[half * 8 + 1][row] = xa.y;
            As[half * 8 + 2][row] = xa.z; As[half * 8 + 3][row] = xa.w;
            As[half * 8 + 4][row] = xb.x; As[half * 8 + 5][row] = xb.y;
            As[half * 8 + 6][row] = xb.z; As[half * 8 + 7][row] = xb.w;
        } else {
            #pragma unroll
            for (int j = 0; j < 8; j++) As[half * 8 + j][row] = 0.f;
        }
        Bs[half * 8 + 0][row] = wa.x  + sc_row * (float)((q      ) & 0xF);
        Bs[half * 8 + 1][row] = wa.y  + sc_row * (float)((q >>  4) & 0xF);
        Bs[half * 8 + 2][row] = wa.z  + sc_row * (float)((q >>  8) & 0xF);
        Bs[half * 8 + 3][row] = wa.w  + sc_row * (float)((q >> 12) & 0xF);
        Bs[half * 8 + 4][row] = wb4.x + sc_row * (float)((q >> 16) & 0xF);
        Bs[half * 8 + 5][row] = wb4.y + sc_row * (float)((q >> 20) & 0xF);
        Bs[half * 8 + 6][row] = wb4.z + sc_row * (float)((q >> 24) & 0xF);
        Bs[half * 8 + 7][row] = wb4.w + sc_row * (float)((q >> 28) & 0xF);
        __syncthreads();

        if (kt + 1 < K_STEPS) {
            const float* xp = xrow + (kt + 1) * BK;
            const float* wp = wrow + (kt + 1) * BK;
            xa  = *(const float4*)(xp);
            xb  = *(const float4*)(xp + 4);
            wa  = *(const float4*)(wp);
            wb4 = *(const float4*)(wp + 4);
            q   = qrow[(kt + 1) * 2];
        }

        #pragma unroll
        for (int kk = 0; kk < BK; kk++) {
            ulonglong2 aA = *(const ulonglong2*)&As[kk][ty * 4];
            ulonglong2 aB = *(const ulonglong2*)&As[kk][64 + ty * 4];
            float4 b0 = *(const float4*)&Bs[kk][tx * 4];
            float4 b1 = *(const float4*)&Bs[kk][64 + tx * 4];
            unsigned long long a2[4] = { aA.x, aA.y, aB.x, aB.y };
            unsigned long long b2[8] = {
                pack2(b0.x), pack2(b0.y), pack2(b0.z), pack2(b0.w),
                pack2(b1.x), pack2(b1.y), pack2(b1.z), pack2(b1.w) };
            #pragma unroll
            for (int i = 0; i < 4; i++)
                #pragma unroll
                for (int j = 0; j < 8; j++)
                    fma2(acc[i][j], a2[i], b2[j]);
        }
    }

    // Epilogue: out = acc + bias - sc*(z+1)*rowsum
    float bcol[8], szc[8];
    #pragma unroll
    for (int j = 0; j < 8; j++) {
        int col = (j < 4) ? (tx * 4 + j) : (64 + tx * 4 + (j - 4));
        bcol[j] = bias[o0 + col];
        szc[j]  = s_scz[col];
    }
    #pragma unroll
    for (int i2 = 0; i2 < 4; i2++) {
        int rbase = (i2 < 2) ? (ty * 4 + i2 * 2) : (64 + ty * 4 + (i2 - 2) * 2);
        float2 c[8];
        #pragma unroll
        for (int j = 0; j < 8; j++) c[j] = unpack2(acc[i2][j]);
        #pragma unroll
        for (int h = 0; h < 2; h++) {
            int r  = rbase + h;
            int tk = s_tok[r];
            if (tk < 0) continue;
            float rs = g_rowsum[tk];
            float va[8];
            #pragma unroll
            for (int j = 0; j < 8; j++)
                va[j] = (h ? c[j].y : c[j].x) + bcol[j] - szc[j] * rs;
            float* orow = out + (size_t)tk * OUT_DIM + o0;
            *(float4*)(orow + tx * 4)      = make_float4(va[0], va[1], va[2], va[3]);
            *(float4*)(orow + 64 + tx * 4) = make_float4(va[4], va[5], va[6], va[7]);
        }
    }
}

extern "C" void kernel_launch(void* const* d_in, const int* in_sizes, int n_in,
                              void* d_out, int out_size) {
    const float* x      = (const float*)d_in[0];
    const float* w_base = (const float*)d_in[1];
    const float* bias   = (const float*)d_in[2];
    const int*   qw_q   = (const int*)d_in[3];
    const int*   qw_k   = (const int*)d_in[4];
    const int*   qw_v   = (const int*)d_in[5];
    const int*   qz_q   = (const int*)d_in[6];
    const int*   qz_k   = (const int*)d_in[7];
    const int*   qz_v   = (const int*)d_in[8];
    const float* sc_q   = (const float*)d_in[9];
    const float* sc_k   = (const float*)d_in[10];
    const float* sc_v   = (const float*)d_in[11];
    const int*   indices = (const int*)d_in[12];
    float* out = (float*)d_out;

    reset_kernel<<<1, 32>>>();
    group_kernel<<<4, 256>>>(indices);
    rowsum_kernel<<<T_TOKENS / 8, 256>>>(x);

    dim3 grid(OUT_DIM / BN, NUM_D * (T_TOKENS / BM));
    fused_qkv_delta_kernel<<<grid, 256>>>(
        x, w_base, bias, qw_q, qw_k, qw_v,
        qz_q, qz_k, qz_v, sc_q, sc_k, sc_v, out);
}

// round 4
// speedup vs baseline: 1.4388x; 1.4388x over previous
#include <cuda_runtime.h>
#include <cstdint>

#define T_TOKENS 1024
#define IN_DIM   4096
#define Q_DIM    4096
#define KV_DIM   1024
#define OUT_DIM  6144
#define NUM_D    4

#define BM 128
#define BN 128
#define KC 32
#define NCHUNK (IN_DIM / KC)     // 128

#define ASTRIDE 80               // bytes per smem tile row (conflict-free, 5x16B)
#define TILE_B  (128 * ASTRIDE)  // 10240
#define STAGE_B (4 * TILE_B)     // A_hi, A_lo, B_hi, B_lo = 40960
#define SM_MISC 2048
#define SMEM_TOTAL (SM_MISC + 2 * STAGE_B)   // 83968

__device__ int   g_cnt[NUM_D];
__device__ int   g_perm[NUM_D][T_TOKENS];
__device__ float g_rowsum[T_TOKENS];

__global__ void reset_kernel() {
    if (threadIdx.x < NUM_D) g_cnt[threadIdx.x] = 0;
}

__global__ void group_kernel(const int* __restrict__ indices) {
    int t = blockIdx.x * blockDim.x + threadIdx.x;
    if (t < T_TOKENS) {
        int d = indices[t];
        int pos = atomicAdd(&g_cnt[d], 1);
        g_perm[d][pos] = t;
    }
}

__global__ void rowsum_kernel(const float* __restrict__ x) {
    int warp = (blockIdx.x * blockDim.x + threadIdx.x) >> 5;
    int lane = threadIdx.x & 31;
    if (warp >= T_TOKENS) return;
    const float4* xr = (const float4*)(x + (size_t)warp * IN_DIM);
    float s = 0.f;
    #pragma unroll 4
    for (int i = lane; i < IN_DIM / 4; i += 32) {
        float4 v = xr[i];
        s += (v.x + v.y) + (v.z + v.w);
    }
    #pragma unroll
    for (int off = 16; off > 0; off >>= 1) s += __shfl_down_sync(0xffffffffu, s, off);
    if (lane == 0) g_rowsum[warp] = s;
}

// ------------------------------ helpers -----------------------------------

__device__ __forceinline__ uint32_t smem_u32(const void* p) {
    uint32_t a;
    asm("{ .reg .u64 t; cvta.to.shared.u64 t, %1; cvt.u32.u64 %0, t; }"
        : "=r"(a) : "l"(p));
    return a;
}

__device__ __forceinline__ uint32_t bfpair(float a, float b) {
    // pack truncated-bf16(a) low halfword, truncated-bf16(b) high halfword
    return __byte_perm(__float_as_uint(a), __float_as_uint(b), 0x7632);
}
__device__ __forceinline__ float hi_part(float v) {
    return __uint_as_float(__float_as_uint(v) & 0xFFFF0000u);
}

__device__ __forceinline__ void ldsm4(uint32_t* r, uint32_t addr) {
    asm volatile("ldmatrix.sync.aligned.m8n8.x4.shared.b16 {%0,%1,%2,%3}, [%4];"
                 : "=r"(r[0]), "=r"(r[1]), "=r"(r[2]), "=r"(r[3]) : "r"(addr));
}

__device__ __forceinline__ void mma16816(float* c, const uint32_t* a,
                                         uint32_t b0, uint32_t b1) {
    asm volatile(
        "mma.sync.aligned.m16n8k16.row.col.f32.bf16.bf16.f32 "
        "{%0,%1,%2,%3}, {%4,%5,%6,%7}, {%8,%9}, {%0,%1,%2,%3};"
        : "+f"(c[0]), "+f"(c[1]), "+f"(c[2]), "+f"(c[3])
        : "r"(a[0]), "r"(a[1]), "r"(a[2]), "r"(a[3]), "r"(b0), "r"(b1));
}

// split 8 fp32 into bf16 hi tile word4 + lo (residual) word4
__device__ __forceinline__ void split8(const float4 v0, const float4 v1,
                                       uint4& h, uint4& l) {
    h.x = bfpair(v0.x, v0.y); h.y = bfpair(v0.z, v0.w);
    h.z = bfpair(v1.x, v1.y); h.w = bfpair(v1.z, v1.w);
    l.x = bfpair(v0.x - hi_part(v0.x), v0.y - hi_part(v0.y));
    l.y = bfpair(v0.z - hi_part(v0.z), v0.w - hi_part(v0.w));
    l.z = bfpair(v1.x - hi_part(v1.x), v1.y - hi_part(v1.y));
    l.w = bfpair(v1.z - hi_part(v1.z), v1.w - hi_part(v1.w));
}

// --------------------------- main fused kernel ----------------------------

__global__ void __launch_bounds__(256)
fused_qkv_delta_mma(
    const float* __restrict__ x, const float* __restrict__ w_base,
    const float* __restrict__ bias,
    const int* __restrict__ qw_q, const int* __restrict__ qw_k, const int* __restrict__ qw_v,
    const int* __restrict__ qz_q, const int* __restrict__ qz_k, const int* __restrict__ qz_v,
    const float* __restrict__ sc_q, const float* __restrict__ sc_k, const float* __restrict__ sc_v,
    float* __restrict__ out)
{
    const int d      = blockIdx.y >> 3;
    const int tile   = blockIdx.y & 7;
    const int cnt    = g_cnt[d];
    const int tstart = tile * BM;
    if (tstart >= cnt) return;
    const int nrows = min(BM, cnt - tstart);

    const int o0 = blockIdx.x * BN;
    const int* qw; const int* qz; const float* sc; int ol;
    if (o0 < Q_DIM) {
        ol = o0;
        qw = qw_q + (size_t)d * Q_DIM * (IN_DIM / 8);
        qz = qz_q + d * (Q_DIM / 8);
        sc = sc_q + d * Q_DIM;
    } else if (o0 < Q_DIM + KV_DIM) {
        ol = o0 - Q_DIM;
        qw = qw_k + (size_t)d * KV_DIM * (IN_DIM / 8);
        qz = qz_k + d * (KV_DIM / 8);
        sc = sc_k + d * KV_DIM;
    } else {
        ol = o0 - Q_DIM - KV_DIM;
        qw = qw_v + (size_t)d * KV_DIM * (IN_DIM / 8);
        qz = qz_v + d * (KV_DIM / 8);
        sc = sc_v + d * KV_DIM;
    }

    extern __shared__ __align__(128) char smem[];
    const uint32_t sbase = smem_u32(smem);
    int*   s_tok  = (int*)smem;
    float* s_scz  = (float*)(smem + 512);
    float* s_bias = (float*)(smem + 1024);

    const int tid  = threadIdx.x;
    const int wid  = tid >> 5;
    const int lane = tid & 31;
    const int row  = tid & 127;      // tile row this thread stages
    const int half = tid >> 7;       // which 16 of the 32-k chunk

    if (tid < BM) {
        s_tok[tid] = (tid < nrows) ? g_perm[d][tstart + tid] : -1;
    } else {
        int r  = tid - BM;
        int og = ol + r;
        int z  = (qz[og >> 3] >> ((og & 7) * 4)) & 0xF;
        s_scz[r]  = sc[og] * (float)(z + 1);
        s_bias[r] = bias[o0 + r];
    }
    __syncthreads();

    const int   tok    = s_tok[row];
    const bool  valid  = tok >= 0;
    const float sc_row = sc[ol + row];
    const float4* xrow = (const float4*)(x + (size_t)(valid ? tok : 0) * IN_DIM);
    const float4* wrow = (const float4*)(w_base + (size_t)(o0 + row) * IN_DIM);
    const int*    qrow = qw + (size_t)(ol + row) * (IN_DIM / 8);

    const uint32_t st_off = row * ASTRIDE + half * 32;

    // warp tiling: 2 (M) x 4 (N); warp computes 64x32
    const int wm  = wid & 1;
    const int wn  = wid >> 1;
    const int l15 = lane & 15;
    const int lq  = lane >> 4;   // 0/1 -> k halves for ldmatrix
    const uint32_t a_off0 = (uint32_t)(wm * 64 + l15) * ASTRIDE + lq * 16;
    const uint32_t b_off0 = (uint32_t)(wn * 32 + l15) * ASTRIDE + lq * 16;

    float acc[4][4][4];
    #pragma unroll
    for (int i = 0; i < 4; i++)
        #pragma unroll
        for (int j = 0; j < 4; j++)
            #pragma unroll
            for (int k = 0; k < 4; k++) acc[i][j][k] = 0.f;

    // staging registers for chunk c+1
    float4 xv0, xv1, xv2, xv3, wv0, wv1, wv2, wv3;
    int q0 = 0, q1 = 0;

#define LOAD_STAGE(c) do {                                                    \
    int xi = (c) * 8 + half * 4;                                              \
    if (valid) { xv0 = xrow[xi]; xv1 = xrow[xi+1];                            \
                 xv2 = xrow[xi+2]; xv3 = xrow[xi+3]; }                        \
    wv0 = wrow[xi]; wv1 = wrow[xi+1]; wv2 = wrow[xi+2]; wv3 = wrow[xi+3];     \
    q0 = qrow[(c) * 4 + half * 2]; q1 = qrow[(c) * 4 + half * 2 + 1];         \
} while (0)

#define CONV_STORE(buf) do {                                                  \
    char* A_hi = smem + SM_MISC + (buf) * STAGE_B;                            \
    char* A_lo = A_hi + TILE_B;                                               \
    char* B_hi = A_lo + TILE_B;                                               \
    char* B_lo = B_hi + TILE_B;                                               \
    uint4 h, l;                                                               \
    if (valid) { split8(xv0, xv1, h, l); }                                    \
    else { h = make_uint4(0,0,0,0); l = h; }                                  \
    *(uint4*)(A_hi + st_off) = h; *(uint4*)(A_lo + st_off) = l;               \
    if (valid) { split8(xv2, xv3, h, l); }                                    \
    else { h = make_uint4(0,0,0,0); l = h; }                                  \
    *(uint4*)(A_hi + st_off + 16) = h; *(uint4*)(A_lo + st_off + 16) = l;     \
    float4 c0, c1;                                                            \
    c0.x = fmaf(sc_row, (float)((q0      ) & 0xF), wv0.x);                    \
    c0.y = fmaf(sc_row, (float)((q0 >>  4) & 0xF), wv0.y);                    \
    c0.z = fmaf(sc_row, (float)((q0 >>  8) & 0xF), wv0.z);                    \
    c0.w = fmaf(sc_row, (float)((q0 >> 12) & 0xF), wv0.w);                    \
    c1.x = fmaf(sc_row, (float)((q0 >> 16) & 0xF), wv1.x);                    \
    c1.y = fmaf(sc_row, (float)((q0 >> 20) & 0xF), wv1.y);                    \
    c1.z = fmaf(sc_row, (float)((q0 >> 24) & 0xF), wv1.z);                    \
    c1.w = fmaf(sc_row, (float)((q0 >> 28) & 0xF), wv1.w);                    \
    split8(c0, c1, h, l);                                                     \
    *(uint4*)(B_hi + st_off) = h; *(uint4*)(B_lo + st_off) = l;               \
    c0.x = fmaf(sc_row, (float)((q1      ) & 0xF), wv2.x);                    \
    c0.y = fmaf(sc_row, (float)((q1 >>  4) & 0xF), wv2.y);                    \
    c0.z = fmaf(sc_row, (float)((q1 >>  8) & 0xF), wv2.z);                    \
    c0.w = fmaf(sc_row, (float)((q1 >> 12) & 0xF), wv2.w);                    \
    c1.x = fmaf(sc_row, (float)((q1 >> 16) & 0xF), wv3.x);                    \
    c1.y = fmaf(sc_row, (float)((q1 >> 20) & 0xF), wv3.y);                    \
    c1.z = fmaf(sc_row, (float)((q1 >> 24) & 0xF), wv3.z);                    \
    c1.w = fmaf(sc_row, (float)((q1 >> 28) & 0xF), wv3.w);                    \
    split8(c0, c1, h, l);                                                     \
    *(uint4*)(B_hi + st_off + 16) = h; *(uint4*)(B_lo + st_off + 16) = l;     \
} while (0)

    // prologue: stage chunk 0 into buffer 0
    LOAD_STAGE(0);
    CONV_STORE(0);
    __syncthreads();

    #pragma unroll 1
    for (int c = 0; c < NCHUNK; c++) {
        const int buf = c & 1;
        const bool more = (c + 1 < NCHUNK);
        if (more) LOAD_STAGE(c + 1);

        // ---- MMA on buffer `buf` ----
        {
            const uint32_t base = sbase + SM_MISC + buf * STAGE_B;
            #pragma unroll
            for (int kf = 0; kf < 2; kf++) {
                uint32_t ah[4][4], al[4][4];
                #pragma unroll
                for (int mi = 0; mi < 4; mi++) {
                    ldsm4(ah[mi], base + a_off0 + mi * (16 * ASTRIDE) + kf * 32);
                    ldsm4(al[mi], base + TILE_B + a_off0 + mi * (16 * ASTRIDE) + kf * 32);
                }
                uint32_t bh[2][4], bl[2][4];
                #pragma unroll
                for (int jj = 0; jj < 2; jj++) {
                    ldsm4(bh[jj], base + 2 * TILE_B + b_off0 + jj * (16 * ASTRIDE) + kf * 32);
                    ldsm4(bl[jj], base + 3 * TILE_B + b_off0 + jj * (16 * ASTRIDE) + kf * 32);
                }
                #pragma unroll
                for (int mi = 0; mi < 4; mi++) {
                    #pragma unroll
                    for (int nf = 0; nf < 4; nf++) {
                        const int jj = nf >> 1, s = nf & 1;
                        const uint32_t b0h = bh[jj][s], b1h = bh[jj][s + 2];
                        mma16816(acc[mi][nf], ah[mi], b0h, b1h);
                        mma16816(acc[mi][nf], al[mi], b0h, b1h);
                        mma16816(acc[mi][nf], ah[mi], bl[jj][s], bl[jj][s + 2]);
                    }
                }
            }
        }

        if (more) CONV_STORE(buf ^ 1);
        __syncthreads();
    }

    // ---- epilogue: out = acc + bias - sc*(z+1)*rowsum ----
    #pragma unroll
    for (int mi = 0; mi < 4; mi++) {
        #pragma unroll
        for (int h = 0; h < 2; h++) {
            const int r  = wm * 64 + mi * 16 + h * 8 + (lane >> 2);
            const int tk = s_tok[r];
            if (tk < 0) continue;
            const float rs = g_rowsum[tk];
            float* orow = out + (size_t)tk * OUT_DIM + o0;
            #pragma unroll
            for (int nf = 0; nf < 4; nf++) {
                const int col = wn * 32 + nf * 8 + (lane & 3) * 2;
                float2 v;
                v.x = acc[mi][nf][h * 2 + 0] + s_bias[col]     - s_scz[col]     * rs;
                v.y = acc[mi][nf][h * 2 + 1] + s_bias[col + 1] - s_scz[col + 1] * rs;
                *(float2*)(orow + col) = v;
            }
        }
    }
#undef LOAD_STAGE
#undef CONV_STORE
}

extern "C" void kernel_launch(void* const* d_in, const int* in_sizes, int n_in,
                              void* d_out, int out_size) {
    const float* x      = (const float*)d_in[0];
    const float* w_base = (const float*)d_in[1];
    const float* bias   = (const float*)d_in[2];
    const int*   qw_q   = (const int*)d_in[3];
    const int*   qw_k   = (const int*)d_in[4];
    const int*   qw_v   = (const int*)d_in[5];
    const int*   qz_q   = (const int*)d_in[6];
    const int*   qz_k   = (const int*)d_in[7];
    const int*   qz_v   = (const int*)d_in[8];
    const float* sc_q   = (const float*)d_in[9];
    const float* sc_k   = (const float*)d_in[10];
    const float* sc_v   = (const float*)d_in[11];
    const int*   indices = (const int*)d_in[12];
    float* out = (float*)d_out;

    cudaFuncSetAttribute(fused_qkv_delta_mma,
                         cudaFuncAttributeMaxDynamicSharedMemorySize, SMEM_TOTAL);

    reset_kernel<<<1, 32>>>();
    group_kernel<<<4, 256>>>(indices);
    rowsum_kernel<<<T_TOKENS / 8, 256>>>(x);

    dim3 grid(OUT_DIM / BN, NUM_D * (T_TOKENS / BM));
    fused_qkv_delta_mma<<<grid, 256, SMEM_TOTAL>>>(
        x, w_base, bias, qw_q, qw_k, qw_v,
        qz_q, qz_k, qz_v, sc_q, sc_k, sc_v, out);
}

// round 5
// speedup vs baseline: 1.7773x; 1.2352x over previous
#include <cuda_runtime.h>
#include <cuda_fp16.h>
#include <cstdint>

#define T_TOKENS 1024
#define IN_DIM   4096
#define Q_DIM    4096
#define KV_DIM   1024
#define OUT_DIM  6144
#define NUM_D    4

#define BM 128
#define BN 128
#define KC 32
#define NCHUNK (IN_DIM / KC)     // 128

#define ASTRIDE 80               // bytes per smem tile row (conflict-free, 5x16B)
#define TILE_B  (128 * ASTRIDE)  // 10240
#define STAGE_B (3 * TILE_B)     // A_hi, A_lo, B  = 30720
#define SM_MISC 2048
#define SMEM_TOTAL (SM_MISC + 2 * STAGE_B)   // 63488

__device__ int   g_cnt[NUM_D];
__device__ int   g_perm[NUM_D][T_TOKENS];
__device__ float g_rowsum[T_TOKENS];

__global__ void reset_kernel() {
    if (threadIdx.x < NUM_D) g_cnt[threadIdx.x] = 0;
}

__global__ void group_kernel(const int* __restrict__ indices) {
    int t = blockIdx.x * blockDim.x + threadIdx.x;
    if (t < T_TOKENS) {
        int d = indices[t];
        int pos = atomicAdd(&g_cnt[d], 1);
        g_perm[d][pos] = t;
    }
}

__global__ void rowsum_kernel(const float* __restrict__ x) {
    int warp = (blockIdx.x * blockDim.x + threadIdx.x) >> 5;
    int lane = threadIdx.x & 31;
    if (warp >= T_TOKENS) return;
    const float4* xr = (const float4*)(x + (size_t)warp * IN_DIM);
    float s = 0.f;
    #pragma unroll 4
    for (int i = lane; i < IN_DIM / 4; i += 32) {
        float4 v = xr[i];
        s += (v.x + v.y) + (v.z + v.w);
    }
    #pragma unroll
    for (int off = 16; off > 0; off >>= 1) s += __shfl_down_sync(0xffffffffu, s, off);
    if (lane == 0) g_rowsum[warp] = s;
}

// ------------------------------ helpers -----------------------------------

__device__ __forceinline__ uint32_t smem_u32(const void* p) {
    uint32_t a;
    asm("{ .reg .u64 t; cvta.to.shared.u64 t, %1; cvt.u32.u64 %0, t; }"
        : "=r"(a) : "l"(p));
    return a;
}

__device__ __forceinline__ uint32_t h2pack(float a, float b) {
    __half2 h = __float22half2_rn(make_float2(a, b));
    return *(uint32_t*)&h;
}
__device__ __forceinline__ float2 h2unpack(uint32_t u) {
    __half2 h = *(__half2*)&u;
    return __half22float2(h);
}

__device__ __forceinline__ void ldsm4(uint32_t* r, uint32_t addr) {
    asm volatile("ldmatrix.sync.aligned.m8n8.x4.shared.b16 {%0,%1,%2,%3}, [%4];"
                 : "=r"(r[0]), "=r"(r[1]), "=r"(r[2]), "=r"(r[3]) : "r"(addr));
}

__device__ __forceinline__ void mma16816(float* c, const uint32_t* a,
                                         uint32_t b0, uint32_t b1) {
    asm volatile(
        "mma.sync.aligned.m16n8k16.row.col.f32.f16.f16.f32 "
        "{%0,%1,%2,%3}, {%4,%5,%6,%7}, {%8,%9}, {%0,%1,%2,%3};"
        : "+f"(c[0]), "+f"(c[1]), "+f"(c[2]), "+f"(c[3])
        : "r"(a[0]), "r"(a[1]), "r"(a[2]), "r"(a[3]), "r"(b0), "r"(b1));
}

// split 8 fp32 into fp16 hi word4 + fp16 residual word4 (round-to-nearest)
__device__ __forceinline__ void splitA8(const float4 v0, const float4 v1,
                                        uint4& h, uint4& l) {
    h.x = h2pack(v0.x, v0.y); h.y = h2pack(v0.z, v0.w);
    h.z = h2pack(v1.x, v1.y); h.w = h2pack(v1.z, v1.w);
    float2 f;
    f = h2unpack(h.x); l.x = h2pack(v0.x - f.x, v0.y - f.y);
    f = h2unpack(h.y); l.y = h2pack(v0.z - f.x, v0.w - f.y);
    f = h2unpack(h.z); l.z = h2pack(v1.x - f.x, v1.y - f.y);
    f = h2unpack(h.w); l.w = h2pack(v1.z - f.x, v1.w - f.y);
}

// --------------------------- main fused kernel ----------------------------

__global__ void __launch_bounds__(256, 2)
fused_qkv_delta_mma(
    const float* __restrict__ x, const float* __restrict__ w_base,
    const float* __restrict__ bias,
    const int* __restrict__ qw_q, const int* __restrict__ qw_k, const int* __restrict__ qw_v,
    const int* __restrict__ qz_q, const int* __restrict__ qz_k, const int* __restrict__ qz_v,
    const float* __restrict__ sc_q, const float* __restrict__ sc_k, const float* __restrict__ sc_v,
    float* __restrict__ out)
{
    const int d      = blockIdx.y >> 3;
    const int tile   = blockIdx.y & 7;
    const int cnt    = g_cnt[d];
    const int tstart = tile * BM;
    if (tstart >= cnt) return;
    const int nrows = min(BM, cnt - tstart);

    const int o0 = blockIdx.x * BN;
    const int* qw; const int* qz; const float* sc; int ol;
    if (o0 < Q_DIM) {
        ol = o0;
        qw = qw_q + (size_t)d * Q_DIM * (IN_DIM / 8);
        qz = qz_q + d * (Q_DIM / 8);
        sc = sc_q + d * Q_DIM;
    } else if (o0 < Q_DIM + KV_DIM) {
        ol = o0 - Q_DIM;
        qw = qw_k + (size_t)d * KV_DIM * (IN_DIM / 8);
        qz = qz_k + d * (KV_DIM / 8);
        sc = sc_k + d * KV_DIM;
    } else {
        ol = o0 - Q_DIM - KV_DIM;
        qw = qw_v + (size_t)d * KV_DIM * (IN_DIM / 8);
        qz = qz_v + d * (KV_DIM / 8);
        sc = sc_v + d * KV_DIM;
    }

    extern __shared__ __align__(128) char smem[];
    const uint32_t sbase = smem_u32(smem);
    int*   s_tok  = (int*)smem;
    float* s_scz  = (float*)(smem + 512);
    float* s_bias = (float*)(smem + 1024);

    const int tid  = threadIdx.x;
    const int wid  = tid >> 5;
    const int lane = tid & 31;
    const int row  = tid & 127;      // tile row this thread stages
    const int half = tid >> 7;       // which 16 of the 32-k chunk

    if (tid < BM) {
        s_tok[tid] = (tid < nrows) ? g_perm[d][tstart + tid] : -1;
    } else {
        int r  = tid - BM;
        int og = ol + r;
        int z  = (qz[og >> 3] >> ((og & 7) * 4)) & 0xF;
        s_scz[r]  = sc[og] * (float)(z + 1);
        s_bias[r] = bias[o0 + r];
    }
    __syncthreads();

    const int   tok    = s_tok[row];
    const bool  valid  = tok >= 0;
    const float sc_row = sc[ol + row];
    const float4* xrow = (const float4*)(x + (size_t)(valid ? tok : 0) * IN_DIM);
    const float4* wrow = (const float4*)(w_base + (size_t)(o0 + row) * IN_DIM);
    const int*    qrow = qw + (size_t)(ol + row) * (IN_DIM / 8);

    const uint32_t st_off = row * ASTRIDE + half * 32;

    // warp tiling: 2 (M) x 4 (N); warp computes 64x32
    const int wm  = wid & 1;
    const int wn  = wid >> 1;
    const int l15 = lane & 15;
    const int lq  = lane >> 4;   // 0/1 -> k halves for ldmatrix
    const uint32_t a_off0 = (uint32_t)(wm * 64 + l15) * ASTRIDE + lq * 16;
    const uint32_t b_off0 = (uint32_t)(wn * 32 + l15) * ASTRIDE + lq * 16;

    float acc[4][4][4];
    #pragma unroll
    for (int i = 0; i < 4; i++)
        #pragma unroll
        for (int j = 0; j < 4; j++)
            #pragma unroll
            for (int k = 0; k < 4; k++) acc[i][j][k] = 0.f;

    // staging registers for chunk c+1
    float4 xv0, xv1, xv2, xv3, wv0, wv1, wv2, wv3;
    int q0 = 0, q1 = 0;

#define LOAD_STAGE(c) do {                                                    \
    int xi = (c) * 8 + half * 4;                                              \
    if (valid) { xv0 = xrow[xi]; xv1 = xrow[xi+1];                            \
                 xv2 = xrow[xi+2]; xv3 = xrow[xi+3]; }                        \
    wv0 = wrow[xi]; wv1 = wrow[xi+1]; wv2 = wrow[xi+2]; wv3 = wrow[xi+3];     \
    q0 = qrow[(c) * 4 + half * 2]; q1 = qrow[(c) * 4 + half * 2 + 1];         \
} while (0)

#define CONV_STORE(buf) do {                                                  \
    char* A_hi = smem + SM_MISC + (buf) * STAGE_B;                            \
    char* A_lo = A_hi + TILE_B;                                               \
    char* B_t  = A_lo + TILE_B;                                               \
    uint4 h, l;                                                               \
    if (valid) { splitA8(xv0, xv1, h, l); }                                   \
    else { h = make_uint4(0,0,0,0); l = h; }                                  \
    *(uint4*)(A_hi + st_off) = h; *(uint4*)(A_lo + st_off) = l;               \
    if (valid) { splitA8(xv2, xv3, h, l); }                                   \
    else { h = make_uint4(0,0,0,0); l = h; }                                  \
    *(uint4*)(A_hi + st_off + 16) = h; *(uint4*)(A_lo + st_off + 16) = l;     \
    float c0, c1, c2, c3, c4, c5, c6, c7;                                     \
    c0 = fmaf(sc_row, (float)((q0      ) & 0xF), wv0.x);                      \
    c1 = fmaf(sc_row, (float)((q0 >>  4) & 0xF), wv0.y);                      \
    c2 = fmaf(sc_row, (float)((q0 >>  8) & 0xF), wv0.z);                      \
    c3 = fmaf(sc_row, (float)((q0 >> 12) & 0xF), wv0.w);                      \
    c4 = fmaf(sc_row, (float)((q0 >> 16) & 0xF), wv1.x);                      \
    c5 = fmaf(sc_row, (float)((q0 >> 20) & 0xF), wv1.y);                      \
    c6 = fmaf(sc_row, (float)((q0 >> 24) & 0xF), wv1.z);                      \
    c7 = fmaf(sc_row, (float)((q0 >> 28) & 0xF), wv1.w);                      \
    h.x = h2pack(c0, c1); h.y = h2pack(c2, c3);                               \
    h.z = h2pack(c4, c5); h.w = h2pack(c6, c7);                               \
    *(uint4*)(B_t + st_off) = h;                                              \
    c0 = fmaf(sc_row, (float)((q1      ) & 0xF), wv2.x);                      \
    c1 = fmaf(sc_row, (float)((q1 >>  4) & 0xF), wv2.y);                      \
    c2 = fmaf(sc_row, (float)((q1 >>  8) & 0xF), wv2.z);                      \
    c3 = fmaf(sc_row, (float)((q1 >> 12) & 0xF), wv2.w);                      \
    c4 = fmaf(sc_row, (float)((q1 >> 16) & 0xF), wv3.x);                      \
    c5 = fmaf(sc_row, (float)((q1 >> 20) & 0xF), wv3.y);                      \
    c6 = fmaf(sc_row, (float)((q1 >> 24) & 0xF), wv3.z);                      \
    c7 = fmaf(sc_row, (float)((q1 >> 28) & 0xF), wv3.w);                      \
    h.x = h2pack(c0, c1); h.y = h2pack(c2, c3);                               \
    h.z = h2pack(c4, c5); h.w = h2pack(c6, c7);                               \
    *(uint4*)(B_t + st_off + 16) = h;                                         \
} while (0)

    // prologue: stage chunk 0 into buffer 0
    LOAD_STAGE(0);
    CONV_STORE(0);
    __syncthreads();

    #pragma unroll 1
    for (int c = 0; c < NCHUNK; c++) {
        const int buf = c & 1;
        const bool more = (c + 1 < NCHUNK);
        if (more) LOAD_STAGE(c + 1);

        // ---- MMA on buffer `buf` ----
        {
            const uint32_t base = sbase + SM_MISC + buf * STAGE_B;
            #pragma unroll
            for (int kf = 0; kf < 2; kf++) {
                uint32_t ah[4][4], al[4][4];
                #pragma unroll
                for (int mi = 0; mi < 4; mi++) {
                    ldsm4(ah[mi], base + a_off0 + mi * (16 * ASTRIDE) + kf * 32);
                    ldsm4(al[mi], base + TILE_B + a_off0 + mi * (16 * ASTRIDE) + kf * 32);
                }
                uint32_t bh[2][4];
                #pragma unroll
                for (int jj = 0; jj < 2; jj++) {
                    ldsm4(bh[jj], base + 2 * TILE_B + b_off0 + jj * (16 * ASTRIDE) + kf * 32);
                }
                #pragma unroll
                for (int mi = 0; mi < 4; mi++) {
                    #pragma unroll
                    for (int nf = 0; nf < 4; nf++) {
                        const int jj = nf >> 1, s = nf & 1;
                        const uint32_t b0 = bh[jj][s], b1 = bh[jj][s + 2];
                        mma16816(acc[mi][nf], ah[mi], b0, b1);
                        mma16816(acc[mi][nf], al[mi], b0, b1);
                    }
                }
            }
        }

        if (more) CONV_STORE(buf ^ 1);
        __syncthreads();
    }

    // ---- epilogue: out = acc + bias - sc*(z+1)*rowsum ----
    #pragma unroll
    for (int mi = 0; mi < 4; mi++) {
        #pragma unroll
        for (int h = 0; h < 2; h++) {
            const int r  = wm * 64 + mi * 16 + h * 8 + (lane >> 2);
            const int tk = s_tok[r];
            if (tk < 0) continue;
            const float rs = g_rowsum[tk];
            float* orow = out + (size_t)tk * OUT_DIM + o0;
            #pragma unroll
            for (int nf = 0; nf < 4; nf++) {
                const int col = wn * 32 + nf * 8 + (lane & 3) * 2;
                float2 v;
                v.x = acc[mi][nf][h * 2 + 0] + s_bias[col]     - s_scz[col]     * rs;
                v.y = acc[mi][nf][h * 2 + 1] + s_bias[col + 1] - s_scz[col + 1] * rs;
                *(float2*)(orow + col) = v;
            }
        }
    }
#undef LOAD_STAGE
#undef CONV_STORE
}

extern "C" void kernel_launch(void* const* d_in, const int* in_sizes, int n_in,
                              void* d_out, int out_size) {
    const float* x      = (const float*)d_in[0];
    const float* w_base = (const float*)d_in[1];
    const float* bias   = (const float*)d_in[2];
    const int*   qw_q   = (const int*)d_in[3];
    const int*   qw_k   = (const int*)d_in[4];
    const int*   qw_v   = (const int*)d_in[5];
    const int*   qz_q   = (const int*)d_in[6];
    const int*   qz_k   = (const int*)d_in[7];
    const int*   qz_v   = (const int*)d_in[8];
    const float* sc_q   = (const float*)d_in[9];
    const float* sc_k   = (const float*)d_in[10];
    const float* sc_v   = (const float*)d_in[11];
    const int*   indices = (const int*)d_in[12];
    float* out = (float*)d_out;

    cudaFuncSetAttribute(fused_qkv_delta_mma,
                         cudaFuncAttributeMaxDynamicSharedMemorySize, SMEM_TOTAL);

    reset_kernel<<<1, 32>>>();
    group_kernel<<<4, 256>>>(indices);
    rowsum_kernel<<<T_TOKENS / 8, 256>>>(x);

    dim3 grid(OUT_DIM / BN, NUM_D * (T_TOKENS / BM));
    fused_qkv_delta_mma<<<grid, 256, SMEM_TOTAL>>>(
        x, w_base, bias, qw_q, qw_k, qw_v,
        qz_q, qz_k, qz_v, sc_q, sc_k, sc_v, out);
}

// round 6
// speedup vs baseline: 1.9579x; 1.1016x over previous
#include <cuda_runtime.h>
#include <cuda_fp16.h>
#include <cstdint>

#define T_TOKENS 1024
#define IN_DIM   4096
#define Q_DIM    4096
#define KV_DIM   1024
#define OUT_DIM  6144
#define NUM_D    4

#define BM 128
#define BN 128
#define KC 32
#define NCHUNK (IN_DIM / KC)     // 128

#define ASTRIDE 80               // bytes per smem tile row (conflict-free, 5x16B)
#define TILE_B  (128 * ASTRIDE)  // 10240
#define STAGE_B (2 * TILE_B)     // A, B = 20480
#define SM_MISC 2048
#define SMEM_TOTAL (SM_MISC + 2 * STAGE_B)   // 43008

__device__ int   g_cnt[NUM_D];
__device__ int   g_perm[NUM_D][T_TOKENS];
__device__ float g_rowsum[T_TOKENS];

__global__ void reset_kernel() {
    if (threadIdx.x < NUM_D) g_cnt[threadIdx.x] = 0;
}

__global__ void group_kernel(const int* __restrict__ indices) {
    int t = blockIdx.x * blockDim.x + threadIdx.x;
    if (t < T_TOKENS) {
        int d = indices[t];
        int pos = atomicAdd(&g_cnt[d], 1);
        g_perm[d][pos] = t;
    }
}

__global__ void rowsum_kernel(const float* __restrict__ x) {
    int warp = (blockIdx.x * blockDim.x + threadIdx.x) >> 5;
    int lane = threadIdx.x & 31;
    if (warp >= T_TOKENS) return;
    const float4* xr = (const float4*)(x + (size_t)warp * IN_DIM);
    float s = 0.f;
    #pragma unroll 4
    for (int i = lane; i < IN_DIM / 4; i += 32) {
        float4 v = xr[i];
        s += (v.x + v.y) + (v.z + v.w);
    }
    #pragma unroll
    for (int off = 16; off > 0; off >>= 1) s += __shfl_down_sync(0xffffffffu, s, off);
    if (lane == 0) g_rowsum[warp] = s;
}

// ------------------------------ helpers -----------------------------------

__device__ __forceinline__ uint32_t smem_u32(const void* p) {
    uint32_t a;
    asm("{ .reg .u64 t; cvta.to.shared.u64 t, %1; cvt.u32.u64 %0, t; }"
        : "=r"(a) : "l"(p));
    return a;
}

__device__ __forceinline__ uint32_t h2pack(float a, float b) {
    __half2 h = __float22half2_rn(make_float2(a, b));
    return *(uint32_t*)&h;
}

__device__ __forceinline__ void ldsm4(uint32_t* r, uint32_t addr) {
    asm volatile("ldmatrix.sync.aligned.m8n8.x4.shared.b16 {%0,%1,%2,%3}, [%4];"
                 : "=r"(r[0]), "=r"(r[1]), "=r"(r[2]), "=r"(r[3]) : "r"(addr));
}

__device__ __forceinline__ void mma16816(float* c, const uint32_t* a,
                                         uint32_t b0, uint32_t b1) {
    asm volatile(
        "mma.sync.aligned.m16n8k16.row.col.f32.f16.f16.f32 "
        "{%0,%1,%2,%3}, {%4,%5,%6,%7}, {%8,%9}, {%0,%1,%2,%3};"
        : "+f"(c[0]), "+f"(c[1]), "+f"(c[2]), "+f"(c[3])
        : "r"(a[0]), "r"(a[1]), "r"(a[2]), "r"(a[3]), "r"(b0), "r"(b1));
}

// --------------------------- main fused kernel ----------------------------

__global__ void __launch_bounds__(256, 2)
fused_qkv_delta_mma(
    const float* __restrict__ x, const float* __restrict__ w_base,
    const float* __restrict__ bias,
    const int* __restrict__ qw_q, const int* __restrict__ qw_k, const int* __restrict__ qw_v,
    const int* __restrict__ qz_q, const int* __restrict__ qz_k, const int* __restrict__ qz_v,
    const float* __restrict__ sc_q, const float* __restrict__ sc_k, const float* __restrict__ sc_v,
    float* __restrict__ out)
{
    const int d      = blockIdx.y >> 3;
    const int tile   = blockIdx.y & 7;
    const int cnt    = g_cnt[d];
    const int tstart = tile * BM;
    if (tstart >= cnt) return;
    const int nrows = min(BM, cnt - tstart);

    const int o0 = blockIdx.x * BN;
    const int* qw; const int* qz; const float* sc; int ol;
    if (o0 < Q_DIM) {
        ol = o0;
        qw = qw_q + (size_t)d * Q_DIM * (IN_DIM / 8);
        qz = qz_q + d * (Q_DIM / 8);
        sc = sc_q + d * Q_DIM;
    } else if (o0 < Q_DIM + KV_DIM) {
        ol = o0 - Q_DIM;
        qw = qw_k + (size_t)d * KV_DIM * (IN_DIM / 8);
        qz = qz_k + d * (KV_DIM / 8);
        sc = sc_k + d * KV_DIM;
    } else {
        ol = o0 - Q_DIM - KV_DIM;
        qw = qw_v + (size_t)d * KV_DIM * (IN_DIM / 8);
        qz = qz_v + d * (KV_DIM / 8);
        sc = sc_v + d * KV_DIM;
    }

    extern __shared__ __align__(128) char smem[];
    const uint32_t sbase = smem_u32(smem);
    int*   s_tok  = (int*)smem;
    float* s_scz  = (float*)(smem + 512);
    float* s_bias = (float*)(smem + 1024);

    const int tid  = threadIdx.x;
    const int wid  = tid >> 5;
    const int lane = tid & 31;
    const int row  = tid & 127;      // tile row this thread stages
    const int half = tid >> 7;       // which 16 of the 32-k chunk

    if (tid < BM) {
        s_tok[tid] = (tid < nrows) ? g_perm[d][tstart + tid] : -1;
    } else {
        int r  = tid - BM;
        int og = ol + r;
        int z  = (qz[og >> 3] >> ((og & 7) * 4)) & 0xF;
        s_scz[r]  = sc[og] * (float)(z + 1);
        s_bias[r] = bias[o0 + r];
    }
    __syncthreads();

    const int   tok    = s_tok[row];
    const bool  valid  = tok >= 0;
    const float sc_row = sc[ol + row];
    const float4* xrow = (const float4*)(x + (size_t)(valid ? tok : 0) * IN_DIM);
    const float4* wrow = (const float4*)(w_base + (size_t)(o0 + row) * IN_DIM);
    const int*    qrow = qw + (size_t)(ol + row) * (IN_DIM / 8);

    const uint32_t st_off = row * ASTRIDE + half * 32;

    // warp tiling: 2 (M) x 4 (N); warp computes 64x32
    const int wm  = wid & 1;
    const int wn  = wid >> 1;
    const int l15 = lane & 15;
    const int lq  = lane >> 4;   // 0/1 -> k halves for ldmatrix
    const uint32_t a_off0 = (uint32_t)(wm * 64 + l15) * ASTRIDE + lq * 16;
    const uint32_t b_off0 = (uint32_t)(wn * 32 + l15) * ASTRIDE + lq * 16;

    float acc[4][4][4];
    #pragma unroll
    for (int i = 0; i < 4; i++)
        #pragma unroll
        for (int j = 0; j < 4; j++)
            #pragma unroll
            for (int k = 0; k < 4; k++) acc[i][j][k] = 0.f;

    // staging registers for chunk c+1
    float4 xv0, xv1, xv2, xv3, wv0, wv1, wv2, wv3;
    int q0 = 0, q1 = 0;

#define LOAD_STAGE(c) do {                                                    \
    int xi = (c) * 8 + half * 4;                                              \
    if (valid) { xv0 = xrow[xi]; xv1 = xrow[xi+1];                            \
                 xv2 = xrow[xi+2]; xv3 = xrow[xi+3]; }                        \
    wv0 = wrow[xi]; wv1 = wrow[xi+1]; wv2 = wrow[xi+2]; wv3 = wrow[xi+3];     \
    q0 = qrow[(c) * 4 + half * 2]; q1 = qrow[(c) * 4 + half * 2 + 1];         \
} while (0)

#define CONV_STORE(buf) do {                                                  \
    char* A_t = smem + SM_MISC + (buf) * STAGE_B;                             \
    char* B_t = A_t + TILE_B;                                                 \
    uint4 h;                                                                  \
    if (valid) {                                                              \
        h.x = h2pack(xv0.x, xv0.y); h.y = h2pack(xv0.z, xv0.w);               \
        h.z = h2pack(xv1.x, xv1.y); h.w = h2pack(xv1.z, xv1.w);               \
    } else h = make_uint4(0, 0, 0, 0);                                        \
    *(uint4*)(A_t + st_off) = h;                                              \
    if (valid) {                                                              \
        h.x = h2pack(xv2.x, xv2.y); h.y = h2pack(xv2.z, xv2.w);               \
        h.z = h2pack(xv3.x, xv3.y); h.w = h2pack(xv3.z, xv3.w);               \
    } else h = make_uint4(0, 0, 0, 0);                                        \
    *(uint4*)(A_t + st_off + 16) = h;                                         \
    float c0, c1, c2, c3, c4, c5, c6, c7;                                     \
    c0 = fmaf(sc_row, (float)((q0      ) & 0xF), wv0.x);                      \
    c1 = fmaf(sc_row, (float)((q0 >>  4) & 0xF), wv0.y);                      \
    c2 = fmaf(sc_row, (float)((q0 >>  8) & 0xF), wv0.z);                      \
    c3 = fmaf(sc_row, (float)((q0 >> 12) & 0xF), wv0.w);                      \
    c4 = fmaf(sc_row, (float)((q0 >> 16) & 0xF), wv1.x);                      \
    c5 = fmaf(sc_row, (float)((q0 >> 20) & 0xF), wv1.y);                      \
    c6 = fmaf(sc_row, (float)((q0 >> 24) & 0xF), wv1.z);                      \
    c7 = fmaf(sc_row, (float)((q0 >> 28) & 0xF), wv1.w);                      \
    h.x = h2pack(c0, c1); h.y = h2pack(c2, c3);                               \
    h.z = h2pack(c4, c5); h.w = h2pack(c6, c7);                               \
    *(uint4*)(B_t + st_off) = h;                                              \
    c0 = fmaf(sc_row, (float)((q1      ) & 0xF), wv2.x);                      \
    c1 = fmaf(sc_row, (float)((q1 >>  4) & 0xF), wv2.y);                      \
    c2 = fmaf(sc_row, (float)((q1 >>  8) & 0xF), wv2.z);                      \
    c3 = fmaf(sc_row, (float)((q1 >> 12) & 0xF), wv2.w);                      \
    c4 = fmaf(sc_row, (float)((q1 >> 16) & 0xF), wv3.x);                      \
    c5 = fmaf(sc_row, (float)((q1 >> 20) & 0xF), wv3.y);                      \
    c6 = fmaf(sc_row, (float)((q1 >> 24) & 0xF), wv3.z);                      \
    c7 = fmaf(sc_row, (float)((q1 >> 28) & 0xF), wv3.w);                      \
    h.x = h2pack(c0, c1); h.y = h2pack(c2, c3);                               \
    h.z = h2pack(c4, c5); h.w = h2pack(c6, c7);                               \
    *(uint4*)(B_t + st_off + 16) = h;                                         \
} while (0)

    // prologue: stage chunk 0 into buffer 0
    LOAD_STAGE(0);
    CONV_STORE(0);
    __syncthreads();

    #pragma unroll 1
    for (int c = 0; c < NCHUNK; c++) {
        const int buf = c & 1;
        const bool more = (c + 1 < NCHUNK);
        if (more) LOAD_STAGE(c + 1);

        // ---- MMA on buffer `buf` ----
        {
            const uint32_t base = sbase + SM_MISC + buf * STAGE_B;
            #pragma unroll
            for (int kf = 0; kf < 2; kf++) {
                uint32_t ah[4][4];
                #pragma unroll
                for (int mi = 0; mi < 4; mi++)
                    ldsm4(ah[mi], base + a_off0 + mi * (16 * ASTRIDE) + kf * 32);
                uint32_t bh[2][4];
                #pragma unroll
                for (int jj = 0; jj < 2; jj++)
                    ldsm4(bh[jj], base + TILE_B + b_off0 + jj * (16 * ASTRIDE) + kf * 32);
                #pragma unroll
                for (int mi = 0; mi < 4; mi++) {
                    #pragma unroll
                    for (int nf = 0; nf < 4; nf++) {
                        const int jj = nf >> 1, s = nf & 1;
                        mma16816(acc[mi][nf], ah[mi], bh[jj][s], bh[jj][s + 2]);
                    }
                }
            }
        }

        if (more) CONV_STORE(buf ^ 1);
        __syncthreads();
    }

    // ---- epilogue: out = acc + bias - sc*(z+1)*rowsum ----
    #pragma unroll
    for (int mi = 0; mi < 4; mi++) {
        #pragma unroll
        for (int h = 0; h < 2; h++) {
            const int r  = wm * 64 + mi * 16 + h * 8 + (lane >> 2);
            const int tk = s_tok[r];
            if (tk < 0) continue;
            const float rs = g_rowsum[tk];
            float* orow = out + (size_t)tk * OUT_DIM + o0;
            #pragma unroll
            for (int nf = 0; nf < 4; nf++) {
                const int col = wn * 32 + nf * 8 + (lane & 3) * 2;
                float2 v;
                v.x = acc[mi][nf][h * 2 + 0] + s_bias[col]     - s_scz[col]     * rs;
                v.y = acc[mi][nf][h * 2 + 1] + s_bias[col + 1] - s_scz[col + 1] * rs;
                *(float2*)(orow + col) = v;
            }
        }
    }
#undef LOAD_STAGE
#undef CONV_STORE
}

extern "C" void kernel_launch(void* const* d_in, const int* in_sizes, int n_in,
                              void* d_out, int out_size) {
    const float* x      = (const float*)d_in[0];
    const float* w_base = (const float*)d_in[1];
    const float* bias   = (const float*)d_in[2];
    const int*   qw_q   = (const int*)d_in[3];
    const int*   qw_k   = (const int*)d_in[4];
    const int*   qw_v   = (const int*)d_in[5];
    const int*   qz_q   = (const int*)d_in[6];
    const int*   qz_k   = (const int*)d_in[7];
    const int*   qz_v   = (const int*)d_in[8];
    const float* sc_q   = (const float*)d_in[9];
    const float* sc_k   = (const float*)d_in[10];
    const float* sc_v   = (const float*)d_in[11];
    const int*   indices = (const int*)d_in[12];
    float* out = (float*)d_out;

    cudaFuncSetAttribute(fused_qkv_delta_mma,
                         cudaFuncAttributeMaxDynamicSharedMemorySize, SMEM_TOTAL);

    reset_kernel<<<1, 32>>>();
    group_kernel<<<4, 256>>>(indices);
    rowsum_kernel<<<T_TOKENS / 8, 256>>>(x);

    dim3 grid(OUT_DIM / BN, NUM_D * (T_TOKENS / BM));
    fused_qkv_delta_mma<<<grid, 256, SMEM_TOTAL>>>(
        x, w_base, bias, qw_q, qw_k, qw_v,
        qz_q, qz_k, qz_v, sc_q, sc_k, sc_v, out);
}

// round 7
// speedup vs baseline: 3.6651x; 1.8720x over previous
#include <cuda_runtime.h>
#include <cuda_fp16.h>
#include <cstdint>

#define T_TOKENS 1024
#define IN_DIM   4096
#define Q_DIM    4096
#define KV_DIM   1024
#define OUT_DIM  6144
#define NUM_D    4

#define BM 128
#define BN 128
#define KC 32
#define NCHUNK (IN_DIM / KC)     // 128

#define ASTRIDE 80               // bytes per smem tile row (conflict-free, 5x16B)
#define TILE_B  (128 * ASTRIDE)  // 10240
#define STAGE_B (2 * TILE_B)     // A, B = 20480
#define SM_MISC 2048
#define SMEM_TOTAL (SM_MISC + 2 * STAGE_B)   // 43008

__device__ int   g_cnt[NUM_D];
__device__ int   g_perm[NUM_D][T_TOKENS];
__device__ float g_rowsum[T_TOKENS];

__global__ void reset_kernel() {
    if (threadIdx.x < NUM_D) g_cnt[threadIdx.x] = 0;
}

__global__ void group_kernel(const int* __restrict__ indices) {
    int t = blockIdx.x * blockDim.x + threadIdx.x;
    if (t < T_TOKENS) {
        int d = indices[t];
        int pos = atomicAdd(&g_cnt[d], 1);
        g_perm[d][pos] = t;
    }
}

__global__ void rowsum_kernel(const float* __restrict__ x) {
    int warp = (blockIdx.x * blockDim.x + threadIdx.x) >> 5;
    int lane = threadIdx.x & 31;
    if (warp >= T_TOKENS) return;
    const float4* xr = (const float4*)(x + (size_t)warp * IN_DIM);
    float s = 0.f;
    #pragma unroll 4
    for (int i = lane; i < IN_DIM / 4; i += 32) {
        float4 v = xr[i];
        s += (v.x + v.y) + (v.z + v.w);
    }
    #pragma unroll
    for (int off = 16; off > 0; off >>= 1) s += __shfl_down_sync(0xffffffffu, s, off);
    if (lane == 0) g_rowsum[warp] = s;
}

// ------------------------------ helpers -----------------------------------

__device__ __forceinline__ uint32_t smem_u32(const void* p) {
    uint32_t a;
    asm("{ .reg .u64 t; cvta.to.shared.u64 t, %1; cvt.u32.u64 %0, t; }"
        : "=r"(a) : "l"(p));
    return a;
}

__device__ __forceinline__ uint32_t h2pack(float a, float b) {
    __half2 h = __float22half2_rn(make_float2(a, b));
    return *(uint32_t*)&h;
}

__device__ __forceinline__ void ldsm4(uint32_t* r, uint32_t addr) {
    asm volatile("ldmatrix.sync.aligned.m8n8.x4.shared.b16 {%0,%1,%2,%3}, [%4];"
                 : "=r"(r[0]), "=r"(r[1]), "=r"(r[2]), "=r"(r[3]) : "r"(addr));
}

__device__ __forceinline__ void mma16816(float* c, const uint32_t* a,
                                         uint32_t b0, uint32_t b1) {
    asm volatile(
        "mma.sync.aligned.m16n8k16.row.col.f32.f16.f16.f32 "
        "{%0,%1,%2,%3}, {%4,%5,%6,%7}, {%8,%9}, {%0,%1,%2,%3};"
        : "+f"(c[0]), "+f"(c[1]), "+f"(c[2]), "+f"(c[3])
        : "r"(a[0]), "r"(a[1]), "r"(a[2]), "r"(a[3]), "r"(b0), "r"(b1));
}

// --------------------------- main fused kernel ----------------------------

__global__ void __launch_bounds__(256, 2)
fused_qkv_delta_mma(
    const float* __restrict__ x, const float* __restrict__ w_base,
    const float* __restrict__ bias,
    const int* __restrict__ qw_q, const int* __restrict__ qw_k, const int* __restrict__ qw_v,
    const int* __restrict__ qz_q, const int* __restrict__ qz_k, const int* __restrict__ qz_v,
    const float* __restrict__ sc_q, const float* __restrict__ sc_k, const float* __restrict__ sc_v,
    float* __restrict__ out)
{
    const int d      = blockIdx.y >> 3;
    const int tile   = blockIdx.y & 7;
    const int cnt    = g_cnt[d];
    const int tstart = tile * BM;
    if (tstart >= cnt) return;
    const int nrows = min(BM, cnt - tstart);

    const int o0 = blockIdx.x * BN;
    const int* qw; const int* qz; const float* sc; int ol;
    if (o0 < Q_DIM) {
        ol = o0;
        qw = qw_q + (size_t)d * Q_DIM * (IN_DIM / 8);
        qz = qz_q + d * (Q_DIM / 8);
        sc = sc_q + d * Q_DIM;
    } else if (o0 < Q_DIM + KV_DIM) {
        ol = o0 - Q_DIM;
        qw = qw_k + (size_t)d * KV_DIM * (IN_DIM / 8);
        qz = qz_k + d * (KV_DIM / 8);
        sc = sc_k + d * KV_DIM;
    } else {
        ol = o0 - Q_DIM - KV_DIM;
        qw = qw_v + (size_t)d * KV_DIM * (IN_DIM / 8);
        qz = qz_v + d * (KV_DIM / 8);
        sc = sc_v + d * KV_DIM;
    }

    extern __shared__ __align__(128) char smem[];
    const uint32_t sbase = smem_u32(smem);
    int*   s_tok  = (int*)smem;
    float* s_scz  = (float*)(smem + 512);
    float* s_bias = (float*)(smem + 1024);
    float* s_scw  = (float*)(smem + 1536);

    const int tid  = threadIdx.x;
    const int wid  = tid >> 5;
    const int lane = tid & 31;

    if (tid < BM) {
        s_tok[tid] = (tid < nrows) ? g_perm[d][tstart + tid] : -1;
    } else {
        int r  = tid - BM;
        int og = ol + r;
        int z  = (qz[og >> 3] >> ((og & 7) * 4)) & 0xF;
        s_scz[r]  = sc[og] * (float)(z + 1);
        s_bias[r] = bias[o0 + r];
        s_scw[r]  = sc[og];
    }
    __syncthreads();

    // coalesced staging mapping: thread covers rows {tq, tq+32, tq+64, tq+96},
    // k-quarter fi (floats [fi*4, fi*4+4) of the 32-float chunk)
    const int tq = tid >> 3;
    const int fi = tid & 7;
    const int qsh = (fi & 1) * 16;

    bool  val4[4];
    float scw4[4];
    const float4* xp[4];
    const float4* wp[4];
    const int*    qp[4];
    #pragma unroll
    for (int i = 0; i < 4; i++) {
        const int r   = tq + i * 32;
        const int tk  = s_tok[r];
        val4[i]  = tk >= 0;
        scw4[i]  = s_scw[r];
        xp[i] = (const float4*)(x + (size_t)(val4[i] ? tk : 0) * IN_DIM) + fi;
        wp[i] = (const float4*)(w_base + (size_t)(o0 + r) * IN_DIM) + fi;
        qp[i] = qw + (size_t)(ol + r) * (IN_DIM / 8) + (fi >> 1);
    }

    // warp tiling: 2 (M) x 4 (N); warp computes 64x32
    const int wm  = wid & 1;
    const int wn  = wid >> 1;
    const int l15 = lane & 15;
    const int lq  = lane >> 4;   // 0/1 -> k halves for ldmatrix
    const uint32_t a_off0 = (uint32_t)(wm * 64 + l15) * ASTRIDE + lq * 16;
    const uint32_t b_off0 = (uint32_t)(wn * 32 + l15) * ASTRIDE + lq * 16;

    float acc[4][4][4];
    #pragma unroll
    for (int i = 0; i < 4; i++)
        #pragma unroll
        for (int j = 0; j < 4; j++)
            #pragma unroll
            for (int k = 0; k < 4; k++) acc[i][j][k] = 0.f;

    // staging registers for chunk c+1
    float4 xv[4], wv[4];
    int qv[4];

#define LOAD_STAGE(c) do {                                                    \
    _Pragma("unroll")                                                         \
    for (int i = 0; i < 4; i++) {                                             \
        xv[i] = val4[i] ? xp[i][(c) * 8] : make_float4(0.f, 0.f, 0.f, 0.f);   \
        wv[i] = wp[i][(c) * 8];                                               \
        qv[i] = qp[i][(c) * 4];                                               \
    }                                                                         \
} while (0)

#define CONV_STORE(buf) do {                                                  \
    char* A_t = smem + SM_MISC + (buf) * STAGE_B;                             \
    char* B_t = A_t + TILE_B;                                                 \
    _Pragma("unroll")                                                         \
    for (int i = 0; i < 4; i++) {                                             \
        const uint32_t off = (uint32_t)(tq + i * 32) * ASTRIDE + fi * 8;      \
        uint2 a;                                                              \
        a.x = h2pack(xv[i].x, xv[i].y);                                       \
        a.y = h2pack(xv[i].z, xv[i].w);                                       \
        *(uint2*)(A_t + off) = a;                                             \
        const int   q = qv[i];                                                \
        const float s = scw4[i];                                              \
        float c0 = fmaf(s, (float)((q >> (qsh     )) & 0xF), wv[i].x);        \
        float c1 = fmaf(s, (float)((q >> (qsh +  4)) & 0xF), wv[i].y);        \
        float c2 = fmaf(s, (float)((q >> (qsh +  8)) & 0xF), wv[i].z);        \
        float c3 = fmaf(s, (float)((q >> (qsh + 12)) & 0xF), wv[i].w);        \
        uint2 b;                                                              \
        b.x = h2pack(c0, c1);                                                 \
        b.y = h2pack(c2, c3);                                                 \
        *(uint2*)(B_t + off) = b;                                             \
    }                                                                         \
} while (0)

    // prologue: stage chunk 0 into buffer 0
    LOAD_STAGE(0);
    CONV_STORE(0);
    __syncthreads();

    #pragma unroll 1
    for (int c = 0; c < NCHUNK; c++) {
        const int buf = c & 1;
        const bool more = (c + 1 < NCHUNK);
        if (more) LOAD_STAGE(c + 1);

        // ---- MMA on buffer `buf` ----
        {
            const uint32_t base = sbase + SM_MISC + buf * STAGE_B;
            #pragma unroll
            for (int kf = 0; kf < 2; kf++) {
                uint32_t ah[4][4];
                #pragma unroll
                for (int mi = 0; mi < 4; mi++)
                    ldsm4(ah[mi], base + a_off0 + mi * (16 * ASTRIDE) + kf * 32);
                uint32_t bh[2][4];
                #pragma unroll
                for (int jj = 0; jj < 2; jj++)
                    ldsm4(bh[jj], base + TILE_B + b_off0 + jj * (16 * ASTRIDE) + kf * 32);
                #pragma unroll
                for (int mi = 0; mi < 4; mi++) {
                    #pragma unroll
                    for (int nf = 0; nf < 4; nf++) {
                        const int jj = nf >> 1, s = nf & 1;
                        mma16816(acc[mi][nf], ah[mi], bh[jj][s], bh[jj][s + 2]);
                    }
                }
            }
        }

        if (more) CONV_STORE(buf ^ 1);
        __syncthreads();
    }

    // ---- epilogue: out = acc + bias - sc*(z+1)*rowsum ----
    #pragma unroll
    for (int mi = 0; mi < 4; mi++) {
        #pragma unroll
        for (int h = 0; h < 2; h++) {
            const int r  = wm * 64 + mi * 16 + h * 8 + (lane >> 2);
            const int tk = s_tok[r];
            if (tk < 0) continue;
            const float rs = g_rowsum[tk];
            float* orow = out + (size_t)tk * OUT_DIM + o0;
            #pragma unroll
            for (int nf = 0; nf < 4; nf++) {
                const int col = wn * 32 + nf * 8 + (lane & 3) * 2;
                float2 v;
                v.x = acc[mi][nf][h * 2 + 0] + s_bias[col]     - s_scz[col]     * rs;
                v.y = acc[mi][nf][h * 2 + 1] + s_bias[col + 1] - s_scz[col + 1] * rs;
                *(float2*)(orow + col) = v;
            }
        }
    }
#undef LOAD_STAGE
#undef CONV_STORE
}

extern "C" void kernel_launch(void* const* d_in, const int* in_sizes, int n_in,
                              void* d_out, int out_size) {
    const float* x      = (const float*)d_in[0];
    const float* w_base = (const float*)d_in[1];
    const float* bias   = (const float*)d_in[2];
    const int*   qw_q   = (const int*)d_in[3];
    const int*   qw_k   = (const int*)d_in[4];
    const int*   qw_v   = (const int*)d_in[5];
    const int*   qz_q   = (const int*)d_in[6];
    const int*   qz_k   = (const int*)d_in[7];
    const int*   qz_v   = (const int*)d_in[8];
    const float* sc_q   = (const float*)d_in[9];
    const float* sc_k   = (const float*)d_in[10];
    const float* sc_v   = (const float*)d_in[11];
    const int*   indices = (const int*)d_in[12];
    float* out = (float*)d_out;

    cudaFuncSetAttribute(fused_qkv_delta_mma,
                         cudaFuncAttributeMaxDynamicSharedMemorySize, SMEM_TOTAL);

    reset_kernel<<<1, 32>>>();
    group_kernel<<<4, 256>>>(indices);
    rowsum_kernel<<<T_TOKENS / 8, 256>>>(x);

    dim3 grid(OUT_DIM / BN, NUM_D * (T_TOKENS / BM));
    fused_qkv_delta_mma<<<grid, 256, SMEM_TOTAL>>>(
        x, w_base, bias, qw_q, qw_k, qw_v,
        qz_q, qz_k, qz_v, sc_q, sc_k, sc_v, out);
}

// round 8
// speedup vs baseline: 5.5642x; 1.5181x over previous
#include <cuda_runtime.h>
#include <cuda_fp16.h>
#include <cstdint>

#define T_TOKENS 1024
#define IN_DIM   4096
#define Q_DIM    4096
#define KV_DIM   1024
#define OUT_DIM  6144
#define NUM_D    4

#define BM 128
#define BN 128
#define KC 64
#define NCHUNK (IN_DIM / KC)     // 64

#define XP_ROWS (T_TOKENS + BM)  // 1152 padded rows per adapter

#define ASTRIDE 144              // bytes per smem tile row (128 data + 16 pad)
#define TILE_B  (128 * ASTRIDE)  // 18432
#define STAGE_B (2 * TILE_B)     // A, B = 36864
#define SM_MISC 2048
#define SMEM_TOTAL (SM_MISC + 2 * STAGE_B)   // 75776

__device__ int    g_cnt[NUM_D];
__device__ int    g_perm[NUM_D][T_TOKENS];
__device__ float  g_rowsum[T_TOKENS];
__device__ __half g_wc[(size_t)NUM_D * OUT_DIM * IN_DIM];   // fp16 combined weights
__device__ __half g_xp[(size_t)NUM_D * XP_ROWS * IN_DIM];   // fp16 permuted x

__global__ void reset_kernel() {
    if (threadIdx.x < NUM_D) g_cnt[threadIdx.x] = 0;
}

__global__ void group_kernel(const int* __restrict__ indices) {
    int t = blockIdx.x * blockDim.x + threadIdx.x;
    if (t < T_TOKENS) {
        int d = indices[t];
        int pos = atomicAdd(&g_cnt[d], 1);
        g_perm[d][pos] = t;
    }
}

__global__ void rowsum_kernel(const float* __restrict__ x) {
    int warp = (blockIdx.x * blockDim.x + threadIdx.x) >> 5;
    int lane = threadIdx.x & 31;
    if (warp >= T_TOKENS) return;
    const float4* xr = (const float4*)(x + (size_t)warp * IN_DIM);
    float s = 0.f;
    #pragma unroll 4
    for (int i = lane; i < IN_DIM / 4; i += 32) {
        float4 v = xr[i];
        s += (v.x + v.y) + (v.z + v.w);
    }
    #pragma unroll
    for (int off = 16; off > 0; off >>= 1) s += __shfl_down_sync(0xffffffffu, s, off);
    if (lane == 0) g_rowsum[warp] = s;
}

// ------------------------------ helpers -----------------------------------

__device__ __forceinline__ uint32_t smem_u32(const void* p) {
    uint32_t a;
    asm("{ .reg .u64 t; cvta.to.shared.u64 t, %1; cvt.u32.u64 %0, t; }"
        : "=r"(a) : "l"(p));
    return a;
}

__device__ __forceinline__ uint32_t h2pack(float a, float b) {
    __half2 h = __float22half2_rn(make_float2(a, b));
    return *(uint32_t*)&h;
}

__device__ __forceinline__ void cpa16(uint32_t dst, const void* src) {
    asm volatile("cp.async.ca.shared.global [%0], [%1], 16;"
                 :: "r"(dst), "l"(src) : "memory");
}

__device__ __forceinline__ void ldsm4(uint32_t* r, uint32_t addr) {
    asm volatile("ldmatrix.sync.aligned.m8n8.x4.shared.b16 {%0,%1,%2,%3}, [%4];"
                 : "=r"(r[0]), "=r"(r[1]), "=r"(r[2]), "=r"(r[3]) : "r"(addr));
}

__device__ __forceinline__ void mma16816(float* c, const uint32_t* a,
                                         uint32_t b0, uint32_t b1) {
    asm volatile(
        "mma.sync.aligned.m16n8k16.row.col.f32.f16.f16.f32 "
        "{%0,%1,%2,%3}, {%4,%5,%6,%7}, {%8,%9}, {%0,%1,%2,%3};"
        : "+f"(c[0]), "+f"(c[1]), "+f"(c[2]), "+f"(c[3])
        : "r"(a[0]), "r"(a[1]), "r"(a[2]), "r"(a[3]), "r"(b0), "r"(b1));
}

// ---------------- precompute: fp16 combined weights ------------------------

__global__ void __launch_bounds__(256)
conv_w_kernel(const float* __restrict__ w_base,
              const int* __restrict__ qw_q, const int* __restrict__ qw_k,
              const int* __restrict__ qw_v,
              const float* __restrict__ sc_q, const float* __restrict__ sc_k,
              const float* __restrict__ sc_v)
{
    const int o = blockIdx.x;
    const int t = threadIdx.x;
    const float4* wrow = (const float4*)(w_base + (size_t)o * IN_DIM);

    int ol; const int* qws; const float* scs; size_t dq; int ds;
    if (o < Q_DIM) {
        ol = o; qws = qw_q; scs = sc_q; dq = (size_t)Q_DIM * (IN_DIM / 8); ds = Q_DIM;
    } else if (o < Q_DIM + KV_DIM) {
        ol = o - Q_DIM; qws = qw_k; scs = sc_k; dq = (size_t)KV_DIM * (IN_DIM / 8); ds = KV_DIM;
    } else {
        ol = o - Q_DIM - KV_DIM; qws = qw_v; scs = sc_v; dq = (size_t)KV_DIM * (IN_DIM / 8); ds = KV_DIM;
    }

    float4 w[4];
    #pragma unroll
    for (int i = 0; i < 4; i++) w[i] = wrow[t + 256 * i];

    #pragma unroll
    for (int d = 0; d < NUM_D; d++) {
        const int* qrow = qws + d * dq + (size_t)ol * (IN_DIM / 8);
        const float s = scs[d * ds + ol];
        __half* dst = g_wc + ((size_t)d * OUT_DIM + o) * IN_DIM;
        #pragma unroll
        for (int i = 0; i < 4; i++) {
            const int g  = t + 256 * i;
            const int q  = qrow[g >> 1];
            const int sh = (g & 1) * 16;
            float c0 = fmaf(s, (float)((q >> (sh     )) & 0xF), w[i].x);
            float c1 = fmaf(s, (float)((q >> (sh +  4)) & 0xF), w[i].y);
            float c2 = fmaf(s, (float)((q >> (sh +  8)) & 0xF), w[i].z);
            float c3 = fmaf(s, (float)((q >> (sh + 12)) & 0xF), w[i].w);
            uint2 b;
            b.x = h2pack(c0, c1);
            b.y = h2pack(c2, c3);
            *(uint2*)(dst + (size_t)g * 4) = b;
        }
    }
}

// ---------------- precompute: fp16 permuted activations --------------------

__global__ void __launch_bounds__(256)
conv_x_kernel(const float* __restrict__ x)
{
    const int d = blockIdx.y;
    const int r = blockIdx.x;
    const int cnt  = g_cnt[d];
    const int rcap = (cnt + BM - 1) & ~(BM - 1);
    if (r >= rcap) return;
    const int t = threadIdx.x;
    __half* dst = g_xp + ((size_t)d * XP_ROWS + r) * IN_DIM;
    if (r < cnt) {
        const int tok = g_perm[d][r];
        const float4* src = (const float4*)(x + (size_t)tok * IN_DIM);
        #pragma unroll
        for (int i = 0; i < 4; i++) {
            float4 v = src[t + 256 * i];
            uint2 p;
            p.x = h2pack(v.x, v.y);
            p.y = h2pack(v.z, v.w);
            *(uint2*)(dst + (size_t)(t + 256 * i) * 4) = p;
        }
    } else {
        #pragma unroll
        for (int i = 0; i < 4; i++)
            *(uint2*)(dst + (size_t)(t + 256 * i) * 4) = make_uint2(0, 0);
    }
}

// --------------------------- main fp16 grouped GEMM ------------------------

__global__ void __launch_bounds__(256, 2)
fused_qkv_delta_mma(
    const float* __restrict__ bias,
    const int* __restrict__ qz_q, const int* __restrict__ qz_k, const int* __restrict__ qz_v,
    const float* __restrict__ sc_q, const float* __restrict__ sc_k, const float* __restrict__ sc_v,
    float* __restrict__ out)
{
    const int d      = blockIdx.y >> 3;
    const int tile   = blockIdx.y & 7;
    const int cnt    = g_cnt[d];
    const int tstart = tile * BM;
    if (tstart >= cnt) return;
    const int nrows = min(BM, cnt - tstart);

    const int o0 = blockIdx.x * BN;
    const int* qz; const float* sc; int ol;
    if (o0 < Q_DIM) {
        ol = o0; qz = qz_q + d * (Q_DIM / 8); sc = sc_q + d * Q_DIM;
    } else if (o0 < Q_DIM + KV_DIM) {
        ol = o0 - Q_DIM; qz = qz_k + d * (KV_DIM / 8); sc = sc_k + d * KV_DIM;
    } else {
        ol = o0 - Q_DIM - KV_DIM; qz = qz_v + d * (KV_DIM / 8); sc = sc_v + d * KV_DIM;
    }

    extern __shared__ __align__(128) char smem[];
    const uint32_t sbase = smem_u32(smem);
    int*   s_tok  = (int*)smem;
    float* s_scz  = (float*)(smem + 512);
    float* s_bias = (float*)(smem + 1024);

    const int tid  = threadIdx.x;
    const int wid  = tid >> 5;
    const int lane = tid & 31;

    if (tid < BM) {
        s_tok[tid] = (tid < nrows) ? g_perm[d][tstart + tid] : -1;
    } else {
        int r  = tid - BM;
        int og = ol + r;
        int z  = (qz[og >> 3] >> ((og & 7) * 4)) & 0xF;
        s_scz[r]  = sc[og] * (float)(z + 1);
        s_bias[r] = bias[o0 + r];
    }

    // cp.async source rows (fp16, contiguous)
    const __half* xp_base = g_xp + ((size_t)d * XP_ROWS + tstart) * IN_DIM;
    const __half* wc_base = g_wc + ((size_t)d * OUT_DIM + o0) * IN_DIM;
    const int cr  = tid >> 3;    // staging row 0..31 (+32i)
    const int cq  = tid & 7;     // 16B segment within 128B chunk-row

#define ISSUE_COPIES(cc, buf) do {                                            \
    const uint32_t At = sbase + SM_MISC + (buf) * STAGE_B;                    \
    const uint32_t Bt = At + TILE_B;                                          \
    _Pragma("unroll")                                                         \
    for (int i = 0; i < 4; i++) {                                             \
        const int r = cr + i * 32;                                            \
        const uint32_t doff = (uint32_t)r * ASTRIDE + cq * 16;                \
        cpa16(At + doff, xp_base + (size_t)r * IN_DIM + (cc) * KC + cq * 8);  \
        cpa16(Bt + doff, wc_base + (size_t)r * IN_DIM + (cc) * KC + cq * 8);  \
    }                                                                         \
    asm volatile("cp.async.commit_group;" ::: "memory");                      \
} while (0)

    // warp tiling: 2 (M) x 4 (N); warp computes 64x32
    const int wm  = wid & 1;
    const int wn  = wid >> 1;
    const int l15 = lane & 15;
    const int lq  = lane >> 4;
    const uint32_t a_off0 = (uint32_t)(wm * 64 + l15) * ASTRIDE + lq * 16;
    const uint32_t b_off0 = (uint32_t)(wn * 32 + l15) * ASTRIDE + lq * 16;

    float acc[4][4][4];
    #pragma unroll
    for (int i = 0; i < 4; i++)
        #pragma unroll
        for (int j = 0; j < 4; j++)
            #pragma unroll
            for (int k = 0; k < 4; k++) acc[i][j][k] = 0.f;

    // prologue: copies for chunk 0
    ISSUE_COPIES(0, 0);

    #pragma unroll 1
    for (int c = 0; c < NCHUNK; c++) {
        asm volatile("cp.async.wait_group 0;" ::: "memory");
        __syncthreads();                       // data visible; prev MMA done
        if (c + 1 < NCHUNK) ISSUE_COPIES(c + 1, (c + 1) & 1);

        const uint32_t base = sbase + SM_MISC + (c & 1) * STAGE_B;
        #pragma unroll
        for (int kf = 0; kf < 4; kf++) {
            uint32_t ah[4][4];
            #pragma unroll
            for (int mi = 0; mi < 4; mi++)
                ldsm4(ah[mi], base + a_off0 + mi * (16 * ASTRIDE) + kf * 32);
            uint32_t bh[2][4];
            #pragma unroll
            for (int jj = 0; jj < 2; jj++)
                ldsm4(bh[jj], base + TILE_B + b_off0 + jj * (16 * ASTRIDE) + kf * 32);
            #pragma unroll
            for (int mi = 0; mi < 4; mi++) {
                #pragma unroll
                for (int nf = 0; nf < 4; nf++) {
                    const int jj = nf >> 1, s = nf & 1;
                    mma16816(acc[mi][nf], ah[mi], bh[jj][s], bh[jj][s + 2]);
                }
            }
        }
    }
    __syncthreads();   // ensure s_tok/s_scz/s_bias writes visible (and MMA done)

    // ---- epilogue: out = acc + bias - sc*(z+1)*rowsum ----
    #pragma unroll
    for (int mi = 0; mi < 4; mi++) {
        #pragma unroll
        for (int h = 0; h < 2; h++) {
            const int r  = wm * 64 + mi * 16 + h * 8 + (lane >> 2);
            const int tk = s_tok[r];
            if (tk < 0) continue;
            const float rs = g_rowsum[tk];
            float* orow = out + (size_t)tk * OUT_DIM + o0;
            #pragma unroll
            for (int nf = 0; nf < 4; nf++) {
                const int col = wn * 32 + nf * 8 + (lane & 3) * 2;
                float2 v;
                v.x = acc[mi][nf][h * 2 + 0] + s_bias[col]     - s_scz[col]     * rs;
                v.y = acc[mi][nf][h * 2 + 1] + s_bias[col + 1] - s_scz[col + 1] * rs;
                *(float2*)(orow + col) = v;
            }
        }
    }
#undef ISSUE_COPIES
}

extern "C" void kernel_launch(void* const* d_in, const int* in_sizes, int n_in,
                              void* d_out, int out_size) {
    const float* x      = (const float*)d_in[0];
    const float* w_base = (const float*)d_in[1];
    const float* bias   = (const float*)d_in[2];
    const int*   qw_q   = (const int*)d_in[3];
    const int*   qw_k   = (const int*)d_in[4];
    const int*   qw_v   = (const int*)d_in[5];
    const int*   qz_q   = (const int*)d_in[6];
    const int*   qz_k   = (const int*)d_in[7];
    const int*   qz_v   = (const int*)d_in[8];
    const float* sc_q   = (const float*)d_in[9];
    const float* sc_k   = (const float*)d_in[10];
    const float* sc_v   = (const float*)d_in[11];
    const int*   indices = (const int*)d_in[12];
    float* out = (float*)d_out;

    cudaFuncSetAttribute(fused_qkv_delta_mma,
                         cudaFuncAttributeMaxDynamicSharedMemorySize, SMEM_TOTAL);

    reset_kernel<<<1, 32>>>();
    group_kernel<<<4, 256>>>(indices);
    rowsum_kernel<<<T_TOKENS / 8, 256>>>(x);
    conv_w_kernel<<<OUT_DIM, 256>>>(w_base, qw_q, qw_k, qw_v, sc_q, sc_k, sc_v);
    {
        dim3 g(XP_ROWS, NUM_D);
        conv_x_kernel<<<g, 256>>>(x);
    }

    dim3 grid(OUT_DIM / BN, NUM_D * (T_TOKENS / BM));
    fused_qkv_delta_mma<<<grid, 256, SMEM_TOTAL>>>(
        bias, qz_q, qz_k, qz_v, sc_q, sc_k, sc_v, out);
}